// round 17
// baseline (speedup 1.0000x reference)
#include <cuda_runtime.h>
#include <math.h>
#include <stdint.h>

// ---------------- problem constants ----------------
#define L    12000
#define IN_  1024
#define D_   128
#define ED_  256
#define NST  16
#define DTD  8
#define KC   4
#define NLAY 2
#define EPSV 1e-5f

// chunked scan config: 296 chunks of 41
#define CH  296
#define LC  41
#define PB  96

// ---------------- device scratch (static, no allocation) ----------------
__device__ float g_h    [L * D_];
__device__ float g_hn   [L * D_];
__device__ float g_xz   [L * 2 * ED_];
__device__ float g_xc   [L * ED_];
__device__ float g_dbl  [L * 40];
__device__ float g_y    [L * ED_];
__device__ float g_Aprod[CH * ED_ * NST];
__device__ float g_Bacc [CH * ED_ * NST];
__device__ float g_Hinit[CH * ED_ * NST];
__device__ float g_att  [L];
__device__ float g_part [PB * D_];
__device__ float g_pmax [PB];
__device__ float g_psum [PB];
__device__ float g_sm   [2];          // {M, 1/S}

// ---------------- packed f32x2 helpers ----------------
__device__ __forceinline__ unsigned long long pack2_dup(float v) {
    unsigned long long r;
    asm("mov.b64 %0, {%1, %1};" : "=l"(r) : "f"(v));
    return r;
}
__device__ __forceinline__ void fma2(unsigned long long& d, unsigned long long a,
                                     unsigned long long b) {
    asm("fma.rn.f32x2 %0, %1, %2, %0;" : "+l"(d) : "l"(a), "l"(b));
}
__device__ __forceinline__ void unpack2(unsigned long long v, float& lo, float& hi) {
    asm("mov.b64 {%0, %1}, %2;" : "=f"(lo), "=f"(hi) : "l"(v));
}

// ---------------- SGEMM: 128x64 tile, 8x4 micro-tile, FFMA2, double-buffered ----------------
// C[M,N] = act(A[M,K] @ W[K,N] (+bias)), optional +=
#define BM 128
#define BN 64
#define BK 16
#define TM 8
#define TN 4

__global__ __launch_bounds__(256, 2)
void gemm_kernel(const float* __restrict__ A, const float* __restrict__ W,
                 const float* __restrict__ bias, float* __restrict__ C,
                 int M, int K, int N, int act, int acc)
{
    __shared__ float As[2][BK][BM];   // transposed: As[buf][k][m]
    __shared__ float Ws[2][BK][BN];   // natural:    Ws[buf][k][n]

    const int tid  = threadIdx.x;
    const int row0 = blockIdx.y * BM;
    const int col0 = blockIdx.x * BN;
    const int tx = tid & 15;          // 16 col-groups
    const int ty = tid >> 4;          // 16 row-groups

    unsigned long long acc2[TM / 2][TN];  // lanes = (m, m+1)
    #pragma unroll
    for (int i = 0; i < TM / 2; i++)
        #pragma unroll
        for (int j = 0; j < TN; j++) acc2[i][j] = 0ull;

    float4 aldg[2], wldg;

    auto ldgA = [&](int k0) {
        #pragma unroll
        for (int p = 0; p < 2; p++) {
            const int f = tid + p * 256;
            const int r = f >> 2;
            const int kq = f & 3;
            const int gr = row0 + r;
            if (gr < M)
                aldg[p] = *reinterpret_cast<const float4*>(&A[(size_t)gr * K + k0 + kq * 4]);
            else
                aldg[p] = make_float4(0.f, 0.f, 0.f, 0.f);
        }
    };
    auto ldgW = [&](int k0) {
        const int k  = tid >> 4;
        const int nq = tid & 15;
        const int gn0 = col0 + nq * 4;
        if (gn0 + 3 < N) {
            wldg = *reinterpret_cast<const float4*>(&W[(size_t)(k0 + k) * N + gn0]);
        } else {
            float v[4];
            #pragma unroll
            for (int j = 0; j < 4; j++)
                v[j] = (gn0 + j < N) ? W[(size_t)(k0 + k) * N + gn0 + j] : 0.f;
            wldg = make_float4(v[0], v[1], v[2], v[3]);
        }
    };
    auto sts = [&](int buf) {
        #pragma unroll
        for (int p = 0; p < 2; p++) {
            const int f = tid + p * 256;
            const int r = f >> 2;
            const int kq = f & 3;
            As[buf][kq * 4 + 0][r] = aldg[p].x;
            As[buf][kq * 4 + 1][r] = aldg[p].y;
            As[buf][kq * 4 + 2][r] = aldg[p].z;
            As[buf][kq * 4 + 3][r] = aldg[p].w;
        }
        const int k  = tid >> 4;
        const int nq = tid & 15;
        *reinterpret_cast<float4*>(&Ws[buf][k][nq * 4]) = wldg;
    };

    ldgA(0); ldgW(0);
    sts(0);
    __syncthreads();

    const int KT = K / BK;
    for (int kt = 0; kt < KT; kt++) {
        const int cur = kt & 1;
        if (kt + 1 < KT) { ldgA((kt + 1) * BK); ldgW((kt + 1) * BK); }

        #pragma unroll
        for (int kk = 0; kk < BK; kk++) {
            // a pairs: 8 consecutive floats at As[kk][ty*8] -> 4 u64 (native 16B LDS)
            const ulonglong2* ap =
                reinterpret_cast<const ulonglong2*>(&As[cur][kk][ty * TM]);
            const ulonglong2 av0 = ap[0];
            const ulonglong2 av1 = ap[1];
            unsigned long long a2[4] = {av0.x, av0.y, av1.x, av1.y};
            // w: one 16B LDS + 4 dup movs
            const float4 w4 = *reinterpret_cast<const float4*>(&Ws[cur][kk][tx * TN]);
            unsigned long long w2[4];
            w2[0] = pack2_dup(w4.x); w2[1] = pack2_dup(w4.y);
            w2[2] = pack2_dup(w4.z); w2[3] = pack2_dup(w4.w);
            #pragma unroll
            for (int i = 0; i < 4; i++)
                #pragma unroll
                for (int j = 0; j < 4; j++)
                    fma2(acc2[i][j], a2[i], w2[j]);
        }

        if (kt + 1 < KT) {
            sts((kt + 1) & 1);
            __syncthreads();
        }
    }

    // epilogue
    #pragma unroll
    for (int i = 0; i < TM / 2; i++) {
        const int m0 = row0 + ty * TM + i * 2;
        #pragma unroll
        for (int j = 0; j < TN; j++) {
            const int n = col0 + tx * TN + j;
            if (n >= N) continue;
            float v0, v1;
            unpack2(acc2[i][j], v0, v1);
            const float bb = bias ? bias[n] : 0.f;
            v0 += bb; v1 += bb;
            if (act == 1) {
                v0 = 0.5f * v0 * (1.f + erff(v0 * 0.70710678118654752f));
                v1 = 0.5f * v1 * (1.f + erff(v1 * 0.70710678118654752f));
            } else if (act == 2) {
                v0 = tanhf(v0); v1 = tanhf(v1);
            }
            if (m0 < M) {
                if (acc) C[(size_t)m0 * N + n] += v0;
                else     C[(size_t)m0 * N + n]  = v0;
            }
            if (m0 + 1 < M) {
                if (acc) C[(size_t)(m0 + 1) * N + n] += v1;
                else     C[(size_t)(m0 + 1) * N + n]  = v1;
            }
        }
    }
}

// ---------------- warp-per-row norms (8 rows per 256-thr block) ----------------
__global__ void rmsnorm_kernel(const float* __restrict__ in, const float* __restrict__ w,
                               float* __restrict__ out)
{
    const int wid = threadIdx.x >> 5, lane = threadIdx.x & 31;
    const int row = blockIdx.x * 8 + wid;
    const float4 v = *reinterpret_cast<const float4*>(&in[(size_t)row * D_ + lane * 4]);
    float ss = v.x * v.x + v.y * v.y + v.z * v.z + v.w * v.w;
    #pragma unroll
    for (int o = 16; o; o >>= 1) ss += __shfl_xor_sync(0xffffffffu, ss, o);
    const float sc = rsqrtf(ss * (1.f / D_) + EPSV);
    const float4 wv = *reinterpret_cast<const float4*>(&w[lane * 4]);
    float4 r;
    r.x = v.x * sc * wv.x; r.y = v.y * sc * wv.y;
    r.z = v.z * sc * wv.z; r.w = v.w * sc * wv.w;
    *reinterpret_cast<float4*>(&out[(size_t)row * D_ + lane * 4]) = r;
}

__global__ void layernorm_kernel(const float* __restrict__ in, const float* __restrict__ w,
                                 const float* __restrict__ b, float* __restrict__ out)
{
    const int wid = threadIdx.x >> 5, lane = threadIdx.x & 31;
    const int row = blockIdx.x * 8 + wid;
    const float4 v = *reinterpret_cast<const float4*>(&in[(size_t)row * D_ + lane * 4]);
    float s  = v.x + v.y + v.z + v.w;
    float sq = v.x * v.x + v.y * v.y + v.z * v.z + v.w * v.w;
    #pragma unroll
    for (int o = 16; o; o >>= 1) {
        s  += __shfl_xor_sync(0xffffffffu, s,  o);
        sq += __shfl_xor_sync(0xffffffffu, sq, o);
    }
    const float m  = s * (1.f / D_);
    const float iv = rsqrtf(sq * (1.f / D_) - m * m + EPSV);
    const float4 wv = *reinterpret_cast<const float4*>(&w[lane * 4]);
    const float4 bv = *reinterpret_cast<const float4*>(&b[lane * 4]);
    float4 r;
    r.x = (v.x - m) * iv * wv.x + bv.x; r.y = (v.y - m) * iv * wv.y + bv.y;
    r.z = (v.z - m) * iv * wv.z + bv.z; r.w = (v.w - m) * iv * wv.w + bv.w;
    *reinterpret_cast<float4*>(&out[(size_t)row * D_ + lane * 4]) = r;
}

// ---------------- depthwise causal conv (K=4) + silu: 8 timesteps/thread ----------------
#define CT 8
__global__ void conv_silu_kernel(const float* __restrict__ cw, const float* __restrict__ cb)
{
    const int e = threadIdx.x;                 // channel 0..255
    const int t0 = blockIdx.x * CT;            // 1500 blocks
    const float w0 = cw[e * KC + 0], w1 = cw[e * KC + 1];
    const float w2 = cw[e * KC + 2], w3 = cw[e * KC + 3];
    const float bb = cb[e];
    float h0 = (t0 >= 3) ? g_xz[(size_t)(t0 - 3) * (2 * ED_) + e] : 0.f;
    float h1 = (t0 >= 2) ? g_xz[(size_t)(t0 - 2) * (2 * ED_) + e] : 0.f;
    float h2 = (t0 >= 1) ? g_xz[(size_t)(t0 - 1) * (2 * ED_) + e] : 0.f;
    #pragma unroll
    for (int tt = 0; tt < CT; tt++) {
        const int t = t0 + tt;
        const float cur = g_xz[(size_t)t * (2 * ED_) + e];
        float s = bb;
        s = fmaf(h0, w0, s); s = fmaf(h1, w1, s);
        s = fmaf(h2, w2, s); s = fmaf(cur, w3, s);
        const float sg = 1.f / (1.f + __expf(-s));
        g_xc[(size_t)t * ED_ + e] = s * sg;
        h0 = h1; h1 = h2; h2 = cur;
    }
}

// ---------------- chunked selective scan (delta fused) ----------------
__device__ __forceinline__ float softplus_f(float s) {
    return (s > 0.f) ? (s + log1pf(__expf(-s))) : log1pf(__expf(s));
}

// phase 1: per-chunk (prod dA, local scan with h0=0)
__global__ void scan_pass1(const float* __restrict__ alog,
                           const float* __restrict__ dtw, const float* __restrict__ dtb)
{
    const int e = threadIdx.x;            // 0..255
    const int chunk = blockIdx.x;
    const int t0 = chunk * LC;
    const int tend = min(t0 + LC, L);
    const int nt = tend - t0;

    __shared__ float sB[LC][NST];
    __shared__ float sd[LC][DTD];
    for (int idx = e; idx < nt * NST; idx += ED_) {
        int tt = idx >> 4, n = idx & 15;
        sB[tt][n] = g_dbl[(size_t)(t0 + tt) * 40 + DTD + n];
    }
    for (int idx = e; idx < nt * DTD; idx += ED_) {
        int tt = idx >> 3, k = idx & 7;
        sd[tt][k] = g_dbl[(size_t)(t0 + tt) * 40 + k];
    }
    __syncthreads();

    float Areg[NST], dw[DTD];
    #pragma unroll
    for (int n = 0; n < NST; n++) Areg[n] = -__expf(alog[e * NST + n]);
    #pragma unroll
    for (int k = 0; k < DTD; k++) dw[k] = dtw[k * ED_ + e];
    const float db = dtb[e];

    float h[NST], ap[NST];
    #pragma unroll
    for (int n = 0; n < NST; n++) { h[n] = 0.f; ap[n] = 1.f; }

    for (int tt = 0; tt < nt; tt++) {
        const int t = t0 + tt;
        float sdt = db;
        #pragma unroll
        for (int k = 0; k < DTD; k++) sdt = fmaf(sd[tt][k], dw[k], sdt);
        const float d = softplus_f(sdt);
        const float x = g_xc[(size_t)t * ED_ + e];
        const float dx = d * x;
        #pragma unroll
        for (int n = 0; n < NST; n++) {
            const float a = __expf(d * Areg[n]);
            h[n] = fmaf(a, h[n], dx * sB[tt][n]);
            ap[n] *= a;
        }
    }
    const size_t base = (size_t)chunk * (ED_ * NST) + e * NST;
    #pragma unroll
    for (int n = 0; n < NST; n++) {
        g_Aprod[base + n] = ap[n];
        g_Bacc [base + n] = h[n];
    }
}

// phase 2: sequential combine over chunks, per channel
__global__ void scan_pass2()
{
    const int c = blockIdx.x * blockDim.x + threadIdx.x;  // 0..4095
    float s = 0.f;
    for (int k = 0; k < CH; k++) {
        const size_t idx = (size_t)k * (ED_ * NST) + c;
        g_Hinit[idx] = s;
        s = fmaf(g_Aprod[idx], s, g_Bacc[idx]);
    }
}

// phase 3: replay with correct h0, fused D-skip + silu(z) gate
__global__ void scan_pass3(const float* __restrict__ alog, const float* __restrict__ dp,
                           const float* __restrict__ dtw, const float* __restrict__ dtb)
{
    const int e = threadIdx.x;
    const int chunk = blockIdx.x;
    const int t0 = chunk * LC;
    const int tend = min(t0 + LC, L);
    const int nt = tend - t0;
    if (nt <= 0) return;

    __shared__ float sB[LC][NST];
    __shared__ float sC[LC][NST];
    __shared__ float sd[LC][DTD];
    for (int idx = e; idx < nt * NST; idx += ED_) {
        int tt = idx >> 4, n = idx & 15;
        sB[tt][n] = g_dbl[(size_t)(t0 + tt) * 40 + DTD + n];
        sC[tt][n] = g_dbl[(size_t)(t0 + tt) * 40 + DTD + NST + n];
    }
    for (int idx = e; idx < nt * DTD; idx += ED_) {
        int tt = idx >> 3, k = idx & 7;
        sd[tt][k] = g_dbl[(size_t)(t0 + tt) * 40 + k];
    }
    __syncthreads();

    float Areg[NST], h[NST], dw[DTD];
    #pragma unroll
    for (int n = 0; n < NST; n++) Areg[n] = -__expf(alog[e * NST + n]);
    #pragma unroll
    for (int k = 0; k < DTD; k++) dw[k] = dtw[k * ED_ + e];
    const float db = dtb[e];
    const size_t base = (size_t)chunk * (ED_ * NST) + e * NST;
    #pragma unroll
    for (int n = 0; n < NST; n++) h[n] = g_Hinit[base + n];

    const float dpe = dp[e];
    for (int tt = 0; tt < nt; tt++) {
        const int t = t0 + tt;
        float sdt = db;
        #pragma unroll
        for (int k = 0; k < DTD; k++) sdt = fmaf(sd[tt][k], dw[k], sdt);
        const float d = softplus_f(sdt);
        const float x = g_xc[(size_t)t * ED_ + e];
        const float dx = d * x;
        float y = 0.f;
        #pragma unroll
        for (int n = 0; n < NST; n++) {
            const float a = __expf(d * Areg[n]);
            h[n] = fmaf(a, h[n], dx * sB[tt][n]);
            y = fmaf(h[n], sC[tt][n], y);
        }
        y = fmaf(dpe, x, y);
        const float z = g_xz[(size_t)t * (2 * ED_) + ED_ + e];
        const float sg = 1.f / (1.f + __expf(-z));
        g_y[(size_t)t * ED_ + e] = y * (z * sg);
    }
}

// ---------------- attention score: warp-per-row ----------------
__global__ void att_score_kernel(const float* __restrict__ w2, const float* __restrict__ b2)
{
    const int wid = threadIdx.x >> 5, lane = threadIdx.x & 31;
    const int row = blockIdx.x * 8 + wid;
    const float4 v = *reinterpret_cast<const float4*>(&g_xz[(size_t)row * D_ + lane * 4]);
    const float4 w = *reinterpret_cast<const float4*>(&w2[lane * 4]);
    float s = v.x * w.x + v.y * w.y + v.z * w.z + v.w * w.w;
    #pragma unroll
    for (int o = 16; o; o >>= 1) s += __shfl_xor_sync(0xffffffffu, s, o);
    if (lane == 0) g_att[row] = s + b2[0];
}

// ---------------- softmax phase 1: per-block max & expsum ----------------
__global__ void softmax_partial()
{
    const int b = blockIdx.x, tid = threadIdx.x;   // PB blocks x 128 thr
    const int per = (L + PB - 1) / PB;
    const int t0 = b * per, t1 = min(t0 + per, L);
    float m = -1e30f;
    for (int t = t0 + tid; t < t1; t += 128) m = fmaxf(m, g_att[t]);
    #pragma unroll
    for (int o = 16; o; o >>= 1) m = fmaxf(m, __shfl_xor_sync(0xffffffffu, m, o));
    __shared__ float sm[4];
    if ((tid & 31) == 0) sm[tid >> 5] = m;
    __syncthreads();
    const float bm = fmaxf(fmaxf(sm[0], sm[1]), fmaxf(sm[2], sm[3]));
    float s = 0.f;
    for (int t = t0 + tid; t < t1; t += 128) s += __expf(g_att[t] - bm);
    #pragma unroll
    for (int o = 16; o; o >>= 1) s += __shfl_xor_sync(0xffffffffu, s, o);
    __shared__ float ss[4];
    if ((tid & 31) == 0) ss[tid >> 5] = s;
    __syncthreads();
    if (tid == 0) {
        g_pmax[b] = bm;
        g_psum[b] = ss[0] + ss[1] + ss[2] + ss[3];
    }
}

// ---------------- softmax phase 2: combine ----------------
__global__ void softmax_combine()
{
    const int tid = threadIdx.x;   // 128 >= PB
    float m = (tid < PB) ? g_pmax[tid] : -1e30f;
    #pragma unroll
    for (int o = 16; o; o >>= 1) m = fmaxf(m, __shfl_xor_sync(0xffffffffu, m, o));
    __shared__ float sm[4];
    if ((tid & 31) == 0) sm[tid >> 5] = m;
    __syncthreads();
    const float M = fmaxf(fmaxf(sm[0], sm[1]), fmaxf(sm[2], sm[3]));
    float s = (tid < PB) ? g_psum[tid] * __expf(g_pmax[tid] - M) : 0.f;
    #pragma unroll
    for (int o = 16; o; o >>= 1) s += __shfl_xor_sync(0xffffffffu, s, o);
    __shared__ float ss[4];
    if ((tid & 31) == 0) ss[tid >> 5] = s;
    __syncthreads();
    if (tid == 0) {
        g_sm[0] = M;
        g_sm[1] = 1.f / (ss[0] + ss[1] + ss[2] + ss[3]);
    }
}

// ---------------- pooled = sum_t softmax(att)[t] * hn[t,:] ----------------
__global__ void pooled_part_kernel()
{
    const int b = blockIdx.x, d = threadIdx.x;   // PB blocks x 128 thr
    const int per = (L + PB - 1) / PB;
    const int t0 = b * per, t1 = min(t0 + per, L);
    const float M = g_sm[0], invS = g_sm[1];
    float s = 0.f;
    for (int t = t0; t < t1; t++)
        s = fmaf(__expf(g_att[t] - M), g_hn[(size_t)t * D_ + d], s);
    g_part[b * D_ + d] = s * invS;
}

__global__ void final_kernel(const float* __restrict__ cls_w, const float* __restrict__ cls_b,
                             float* __restrict__ out, int out_size)
{
    const int d = threadIdx.x;  // 128
    float p = 0.f;
    for (int b = 0; b < PB; b++) p += g_part[b * D_ + d];
    float c0 = p * cls_w[d * 2 + 0];
    float c1 = p * cls_w[d * 2 + 1];
    #pragma unroll
    for (int o = 16; o; o >>= 1) {
        c0 += __shfl_xor_sync(0xffffffffu, c0, o);
        c1 += __shfl_xor_sync(0xffffffffu, c1, o);
    }
    __shared__ float s0[4], s1[4];
    if ((d & 31) == 0) { s0[d >> 5] = c0; s1[d >> 5] = c1; }
    __syncthreads();
    if (d == 0) {
        const float l0 = s0[0] + s0[1] + s0[2] + s0[3] + cls_b[0];
        const float l1 = s1[0] + s1[1] + s1[2] + s1[3] + cls_b[1];
        const float mx = fmaxf(l0, l1);
        const float e0 = expf(l0 - mx), e1 = expf(l1 - mx);
        const float den = e0 + e1;
        const float p0 = e0 / den, p1 = e1 / den;
        const float hat = (l1 > l0) ? 1.f : 0.f;
        if (out_size >= 1) out[0] = l0;
        if (out_size >= 2) out[1] = l1;
        if (out_size >= 3) out[2] = p0;
        if (out_size >= 4) out[3] = p1;
        if (out_size >= 5) out[4] = hat;
        for (int i = 5; i < out_size; i++) out[i] = 0.f;
    }
}

// ---------------- host orchestration ----------------
extern "C" void kernel_launch(void* const* d_in, const int* in_sizes, int n_in,
                              void* d_out, int out_size)
{
    const float* x        = (const float*)d_in[0];
    const float* fc1_w    = (const float*)d_in[2];
    const float* fc1_b    = (const float*)d_in[3];
    const float* rms_w    = (const float*)d_in[4];
    const float* inproj_w = (const float*)d_in[5];
    const float* conv_w   = (const float*)d_in[6];
    const float* conv_b   = (const float*)d_in[7];
    const float* xproj_w  = (const float*)d_in[8];
    const float* dt_w     = (const float*)d_in[9];
    const float* dt_b     = (const float*)d_in[10];
    const float* A_log    = (const float*)d_in[11];
    const float* D_p      = (const float*)d_in[12];
    const float* outproj_w= (const float*)d_in[13];
    const float* ln_w     = (const float*)d_in[14];
    const float* ln_b     = (const float*)d_in[15];
    const float* att_w1   = (const float*)d_in[16];
    const float* att_b1   = (const float*)d_in[17];
    const float* att_w2   = (const float*)d_in[18];
    const float* att_b2   = (const float*)d_in[19];
    const float* cls_w    = (const float*)d_in[20];
    const float* cls_b    = (const float*)d_in[21];
    float* out = (float*)d_out;

    float *p_h, *p_hn, *p_xz, *p_xc, *p_dbl, *p_y;
    cudaGetSymbolAddress((void**)&p_h,  g_h);
    cudaGetSymbolAddress((void**)&p_hn, g_hn);
    cudaGetSymbolAddress((void**)&p_xz, g_xz);
    cudaGetSymbolAddress((void**)&p_xc, g_xc);
    cudaGetSymbolAddress((void**)&p_dbl,g_dbl);
    cudaGetSymbolAddress((void**)&p_y,  g_y);

    const int MT = (L + BM - 1) / BM;   // 94 row tiles

    // 1) h = gelu(x @ fc1_w + fc1_b)
    gemm_kernel<<<dim3(D_ / BN, MT), 256>>>(x, fc1_w, fc1_b, p_h,
                                            L, IN_, D_, /*gelu*/1, 0);

    for (int layer = 0; layer < NLAY; layer++) {
        const float* ipw  = inproj_w  + (size_t)layer * D_ * 2 * ED_;
        const float* cw   = conv_w    + (size_t)layer * ED_ * KC;
        const float* cb   = conv_b    + (size_t)layer * ED_;
        const float* xpw  = xproj_w   + (size_t)layer * ED_ * 40;
        const float* dtw  = dt_w      + (size_t)layer * DTD * ED_;
        const float* dtb  = dt_b      + (size_t)layer * ED_;
        const float* alog = A_log     + (size_t)layer * ED_ * NST;
        const float* dp   = D_p       + (size_t)layer * ED_;
        const float* opw  = outproj_w + (size_t)layer * ED_ * D_;
        const float* rw   = rms_w     + (size_t)layer * D_;

        // hn = rmsnorm(h)
        rmsnorm_kernel<<<L / 8, 256>>>(p_h, rw, p_hn);
        // xz = hn @ inproj  (L x 512)
        gemm_kernel<<<dim3((2 * ED_) / BN, MT), 256>>>(p_hn, ipw, nullptr, p_xz,
                                                       L, D_, 2 * ED_, 0, 0);
        // xc = silu(causal_conv(xb))
        conv_silu_kernel<<<L / CT, ED_>>>(cw, cb);
        // dbl = xc @ xproj (L x 40)
        gemm_kernel<<<dim3(1, MT), 256>>>(p_xc, xpw, nullptr, p_dbl,
                                          L, ED_, 40, 0, 0);
        // chunked scan (delta fused)
        scan_pass1<<<CH, ED_>>>(alog, dtw, dtb);
        scan_pass2<<<16, 256>>>();
        scan_pass3<<<CH, ED_>>>(alog, dp, dtw, dtb);
        // h += y @ outproj
        gemm_kernel<<<dim3(D_ / BN, MT), 256>>>(p_y, opw, nullptr, p_h,
                                                L, ED_, D_, 0, /*acc*/1);
    }

    // final layernorm -> hn
    layernorm_kernel<<<L / 8, 256>>>(p_h, ln_w, ln_b, p_hn);
    // s1 = tanh(hn @ att_w1 + b1) -> g_xz (stride 128)
    gemm_kernel<<<dim3(128 / BN, MT), 256>>>(p_hn, att_w1, att_b1, p_xz,
                                             L, D_, 128, /*tanh*/2, 0);
    att_score_kernel<<<L / 8, 256>>>(att_w2, att_b2);
    softmax_partial<<<PB, 128>>>();
    softmax_combine<<<1, 128>>>();
    pooled_part_kernel<<<PB, D_>>>();
    final_kernel<<<1, D_>>>(cls_w, cls_b, out, out_size);
}